// round 6
// baseline (speedup 1.0000x reference)
#include <cuda_runtime.h>
#include <cuda_bf16.h>
#include <math.h>

// LogEig: X = U diag(log w) U^T for 32768 SPD 32x32 fp32 matrices.
// One matrix per warp, lane j owns column j. One-sided Jacobi (SPD: SVD == eig):
//   W <- sym(P); orthogonalize column pairs with Givens rotations (XOR tournament).
//   Converged: column k = sigma_k * u_k  ->  X = sum_k (log sigma_k / sigma_k^2) w_k w_k^T.
// Hot loops use packed fma.rn.f32x2 (2 FMAs/instr, PTX-only on sm_103a).

#define FULLMASK 0xffffffffu
#define WPC 8                 // warps per CTA
#define SROW 36               // padded smem row stride (floats): 144B rows, 16B-aligned, conflict-free transpose
#define MAXSWEEP 14
#define ROTTOL 2.0e-11f       // rotate only if g^2 > ROTTOL*(|wp|^2 |wq|^2): |cos| > ~4.5e-6 (fp32 dot noise floor)

typedef unsigned long long u64;

__device__ __forceinline__ u64 pk2(float lo, float hi) {
    u64 r; asm("mov.b64 %0, {%1, %2};" : "=l"(r) : "f"(lo), "f"(hi)); return r;
}
__device__ __forceinline__ void upk2(u64 v, float& lo, float& hi) {
    asm("mov.b64 {%0, %1}, %2;" : "=f"(lo), "=f"(hi) : "l"(v));
}
__device__ __forceinline__ u64 fma2(u64 a, u64 b, u64 c) {
    u64 d; asm("fma.rn.f32x2 %0, %1, %2, %3;" : "=l"(d) : "l"(a), "l"(b), "l"(c)); return d;
}
__device__ __forceinline__ u64 mul2(u64 a, u64 b) {
    u64 d; asm("mul.rn.f32x2 %0, %1, %2;" : "=l"(d) : "l"(a), "l"(b)); return d;
}

__global__ __launch_bounds__(WPC * 32)
void logeig_kernel(const float* __restrict__ P, float* __restrict__ X, int nmat)
{
    __shared__ float sm[WPC][32 * SROW];

    const int wip  = threadIdx.x >> 5;
    const int lane = threadIdx.x & 31;
    const int mat  = blockIdx.x * WPC + wip;
    if (mat >= nmat) return;

    float* s = sm[wip];
    const float* Pm = P + (size_t)mat * 1024;
    float*       Xm = X + (size_t)mat * 1024;

    // ---- load column `lane` (coalesced) ----
    float wf[32];
    #pragma unroll
    for (int i = 0; i < 32; i++) wf[i] = Pm[i * 32 + lane];          // wf[i] = P[i][lane]

    // ---- symmetrize via padded smem transpose: wf[i] = 0.5*(P[i][lane] + P[lane][i]) ----
    #pragma unroll
    for (int i = 0; i < 32; i += 4)
        *(float4*)&s[lane * SROW + i] = make_float4(wf[i], wf[i+1], wf[i+2], wf[i+3]);
    __syncwarp();
    #pragma unroll
    for (int i = 0; i < 32; i++)
        wf[i] = 0.5f * (wf[i] + s[i * SROW + lane]);                 // stride-1 across lanes: conflict-free
    __syncwarp();

    // ---- pack column into 16 f32x2 registers; exact squared norm ----
    u64 w2[16];
    #pragma unroll
    for (int j = 0; j < 16; j++) w2[j] = pk2(wf[2*j], wf[2*j+1]);

    float n;
    {
        u64 n2 = 0ull;                                                // {0.0f, 0.0f}
        #pragma unroll
        for (int j = 0; j < 16; j++) n2 = fma2(w2[j], w2[j], n2);
        float lo, hi; upk2(n2, lo, hi); n = lo + hi;
    }

    // ---- one-sided Jacobi sweeps ----
    for (int sweep = 0; sweep < MAXSWEEP; ++sweep) {
        bool anyrot = false;
        for (int m = 1; m < 32; ++m) {
            // fetch partner column (shuffle the two 32-bit halves of each packed reg)
            u64 b2[16];
            #pragma unroll
            for (int j = 0; j < 16; j++) {
                float lo, hi; upk2(w2[j], lo, hi);
                const float blo = __shfl_xor_sync(FULLMASK, lo, m);
                const float bhi = __shfl_xor_sync(FULLMASK, hi, m);
                b2[j] = pk2(blo, bhi);
            }
            const float nb = __shfl_xor_sync(FULLMASK, n, m);

            // dot(own, partner): bitwise-identical on both lanes of the pair
            float g;
            {
                u64 g2 = 0ull;
                #pragma unroll
                for (int j = 0; j < 16; j++) g2 = fma2(w2[j], b2[j], g2);
                float lo, hi; upk2(g2, lo, hi); g = lo + hi;
            }

            const bool  isp   = lane < (lane ^ m);                   // lower-index column p?
            const float alpha = isp ? n  : nb;
            const float beta  = isp ? nb : n;

            const bool rot = (g * g > ROTTOL * (alpha * beta));
            anyrot |= rot;

            // Givens: zeta=(beta-alpha)/(2g); t=sgn(zeta)/(|zeta|+sqrt(1+zeta^2)); c=1/sqrt(1+t^2); s=c*t
            const float zeta = __fdividef(beta - alpha, 2.f * g);    // NaN/Inf selected away when !rot
            const float tt   = copysignf(1.f, zeta) / (fabsf(zeta) + sqrtf(fmaf(zeta, zeta, 1.f)));
            float c  = rsqrtf(fmaf(tt, tt, 1.f));
            float ss = c * tt;
            if (!rot) { c = 1.f; ss = 0.f; }

            // w_p' = c*w_p - s*w_q ; w_q' = s*w_p + c*w_q  (+ exact norm refresh)
            const float vcoef = isp ? -ss : ss;
            const u64 c2 = pk2(c, c);
            const u64 v2 = pk2(vcoef, vcoef);
            u64 nn2 = 0ull;
            #pragma unroll
            for (int j = 0; j < 16; j++) {
                u64 t = mul2(c2, w2[j]);
                t = fma2(v2, b2[j], t);
                w2[j] = t;
                nn2 = fma2(t, t, nn2);
            }
            float lo, hi; upk2(nn2, lo, hi); n = lo + hi;
        }
        if (!__any_sync(FULLMASK, anyrot)) break;                    // warp-uniform early exit
    }

    // ---- eigenvalue of own column: sigma^2 = n ----
    const float gcoef = 0.5f * logf(n) / n;                          // log(sigma_k) / sigma_k^2

    // ---- stage converged columns to smem ----
    #pragma unroll
    for (int j = 0; j < 16; j++) {
        float lo, hi; upk2(w2[j], lo, hi);
        s[lane * SROW + 2*j]     = lo;
        s[lane * SROW + 2*j + 1] = hi;
    }
    __syncwarp();

    // ---- X = sum_k gcoef_k * w_k w_k^T : packed rank-1 accumulation ----
    // smem pairs read directly as f32x2 (8B-aligned: SROW*4=144B row base, 8B element steps)
    u64 x2[16];
    #pragma unroll
    for (int j = 0; j < 16; j++) x2[j] = 0ull;

    #pragma unroll 4
    for (int k = 0; k < 32; ++k) {
        const float gk = __shfl_sync(FULLMASK, gcoef, k);
        const float q  = gk * s[k * SROW + lane];                    // gcoef_k * w_k[lane], conflict-free
        const u64 q2 = pk2(q, q);
        const u64* wkrow = (const u64*)&s[k * SROW];                 // broadcast LDS.64 (all lanes same addr)
        #pragma unroll
        for (int j = 0; j < 16; j++)
            x2[j] = fma2(q2, wkrow[j], x2[j]);
    }

    // ---- write column `lane` of X (coalesced per row) ----
    #pragma unroll
    for (int j = 0; j < 16; j++) {
        float lo, hi; upk2(x2[j], lo, hi);
        Xm[(2*j)     * 32 + lane] = lo;
        Xm[(2*j + 1) * 32 + lane] = hi;
    }
}

extern "C" void kernel_launch(void* const* d_in, const int* in_sizes, int n_in,
                              void* d_out, int out_size)
{
    const float* P = (const float*)d_in[0];
    float* X = (float*)d_out;
    const int nmat = in_sizes[0] / 1024;                             // 32x32 per matrix
    dim3 block(WPC * 32);
    dim3 grid((nmat + WPC - 1) / WPC);
    logeig_kernel<<<grid, block>>>(P, X, nmat);
}

// round 7
// speedup vs baseline: 1.1605x; 1.1605x over previous
#include <cuda_runtime.h>
#include <cuda_bf16.h>
#include <math.h>

// LogEig: X = U diag(log w) U^T for 32768 SPD 32x32 fp32 matrices.
// One matrix per warp, lane j owns column j. One-sided Jacobi (SPD: SVD == eig):
//   W <- sym(P); orthogonalize column pairs with Givens rotations (XOR tournament).
//   Converged: column k = sigma_k * u_k  ->  X = sum_k (log sigma_k / sigma_k^2) w_k w_k^T.
// Hot loops use packed fma.rn.f32x2. Norms tracked analytically (alpha' = alpha - t*g),
// exact-refreshed once per sweep; update loop ballot-skipped when no lane rotates.

#define FULLMASK 0xffffffffu
#define WPC 8                 // warps per CTA
#define SROW 36               // padded smem row stride (floats): 144B rows, conflict-free transpose
#define MAXSWEEP 14
#define ROTTOL 1.0e-9f        // rotate only if g^2 > ROTTOL*(|wp|^2 |wq|^2): |cos| > ~3.2e-5

typedef unsigned long long u64;

__device__ __forceinline__ u64 pk2(float lo, float hi) {
    u64 r; asm("mov.b64 %0, {%1, %2};" : "=l"(r) : "f"(lo), "f"(hi)); return r;
}
__device__ __forceinline__ void upk2(u64 v, float& lo, float& hi) {
    asm("mov.b64 {%0, %1}, %2;" : "=f"(lo), "=f"(hi) : "l"(v));
}
__device__ __forceinline__ u64 fma2(u64 a, u64 b, u64 c) {
    u64 d; asm("fma.rn.f32x2 %0, %1, %2, %3;" : "=l"(d) : "l"(a), "l"(b), "l"(c)); return d;
}
__device__ __forceinline__ u64 mul2(u64 a, u64 b) {
    u64 d; asm("mul.rn.f32x2 %0, %1, %2;" : "=l"(d) : "l"(a), "l"(b)); return d;
}
// 4-way-split packed reduction of x[16] (shallow RAW chains), -> scalar sum
__device__ __forceinline__ float redsum16(const u64* a, const u64* b) {
    u64 s0 = 0ull, s1 = 0ull, s2 = 0ull, s3 = 0ull;
    #pragma unroll
    for (int j = 0; j < 16; j += 4) {
        s0 = fma2(a[j],   b[j],   s0);
        s1 = fma2(a[j+1], b[j+1], s1);
        s2 = fma2(a[j+2], b[j+2], s2);
        s3 = fma2(a[j+3], b[j+3], s3);
    }
    float l0,h0,l1,h1,l2,h2,l3,h3;
    upk2(s0,l0,h0); upk2(s1,l1,h1); upk2(s2,l2,h2); upk2(s3,l3,h3);
    return ((l0 + h0) + (l1 + h1)) + ((l2 + h2) + (l3 + h3));
}

__global__ __launch_bounds__(WPC * 32)
void logeig_kernel(const float* __restrict__ P, float* __restrict__ X, int nmat)
{
    __shared__ float sm[WPC][32 * SROW];

    const int wip  = threadIdx.x >> 5;
    const int lane = threadIdx.x & 31;
    const int mat  = blockIdx.x * WPC + wip;
    if (mat >= nmat) return;

    float* s = sm[wip];
    const float* Pm = P + (size_t)mat * 1024;
    float*       Xm = X + (size_t)mat * 1024;

    // ---- load column `lane` (coalesced) ----
    float wf[32];
    #pragma unroll
    for (int i = 0; i < 32; i++) wf[i] = Pm[i * 32 + lane];          // wf[i] = P[i][lane]

    // ---- symmetrize via padded smem transpose ----
    #pragma unroll
    for (int i = 0; i < 32; i += 4)
        *(float4*)&s[lane * SROW + i] = make_float4(wf[i], wf[i+1], wf[i+2], wf[i+3]);
    __syncwarp();
    #pragma unroll
    for (int i = 0; i < 32; i++)
        wf[i] = 0.5f * (wf[i] + s[i * SROW + lane]);                 // conflict-free
    __syncwarp();

    // ---- pack column into 16 f32x2 registers ----
    u64 w2[16];
    #pragma unroll
    for (int j = 0; j < 16; j++) w2[j] = pk2(wf[2*j], wf[2*j+1]);

    float n = redsum16(w2, w2);                                       // exact |w|^2

    // ---- one-sided Jacobi sweeps ----
    for (int sweep = 0; sweep < MAXSWEEP; ++sweep) {
        // exact norm refresh once per sweep (kills analytic-update drift)
        n = fmaxf(redsum16(w2, w2), 1e-30f);

        bool anyrot = false;
        for (int m = 1; m < 32; ++m) {
            // fetch partner column
            u64 b2[16];
            #pragma unroll
            for (int j = 0; j < 16; j++) {
                float lo, hi; upk2(w2[j], lo, hi);
                const float blo = __shfl_xor_sync(FULLMASK, lo, m);
                const float bhi = __shfl_xor_sync(FULLMASK, hi, m);
                b2[j] = pk2(blo, bhi);
            }
            const float nb = __shfl_xor_sync(FULLMASK, n, m);

            // dot(own, partner): bitwise-identical on both lanes of the pair
            const float g = redsum16(w2, b2);

            const bool  isp   = lane < (lane ^ m);                   // lower-index column p?
            const float alpha = isp ? n  : nb;
            const float beta  = isp ? nb : n;

            const bool rot = (g * g > ROTTOL * (alpha * beta));
            const unsigned rmask = __ballot_sync(FULLMASK, rot);
            anyrot |= (rmask != 0u);
            if (!rmask) continue;                                     // warp-uniform skip: nothing to rotate

            // Givens: zeta=(beta-alpha)/(2g); t=sgn(zeta)/(|zeta|+sqrt(1+zeta^2)); c=1/sqrt(1+t^2); s=c*t
            const float zeta = __fdividef(beta - alpha, 2.f * g);    // NaN/Inf selected away when !rot
            const float tt   = copysignf(1.f, zeta) / (fabsf(zeta) + sqrtf(fmaf(zeta, zeta, 1.f)));
            float c  = rsqrtf(fmaf(tt, tt, 1.f));
            float ss = c * tt;
            if (!rot) { c = 1.f; ss = 0.f; }

            // analytic norm update: alpha' = alpha - t*g ; beta' = beta + t*g
            const float nsel = rot ? (isp ? -tt : tt) : 0.f;
            n = fmaxf(fmaf(nsel, g, n), 1e-30f);

            // w_p' = c*w_p - s*w_q ; w_q' = s*w_p + c*w_q
            const float vcoef = isp ? -ss : ss;
            const u64 c2 = pk2(c, c);
            const u64 v2 = pk2(vcoef, vcoef);
            #pragma unroll
            for (int j = 0; j < 16; j++)
                w2[j] = fma2(v2, b2[j], mul2(c2, w2[j]));
        }
        if (!__any_sync(FULLMASK, anyrot)) break;                    // warp-uniform early exit
    }

    // ---- eigenvalue of own column: sigma^2 = n (exact: refreshed at last sweep start,
    //      and the final sweep performed no rotations) ----
    const float gcoef = 0.5f * logf(n) / n;                          // log(sigma_k) / sigma_k^2

    // ---- stage converged columns to smem ----
    #pragma unroll
    for (int j = 0; j < 16; j++) {
        float lo, hi; upk2(w2[j], lo, hi);
        s[lane * SROW + 2*j]     = lo;
        s[lane * SROW + 2*j + 1] = hi;
    }
    __syncwarp();

    // ---- X = sum_k gcoef_k * w_k w_k^T : packed rank-1 accumulation ----
    u64 x2[16];
    #pragma unroll
    for (int j = 0; j < 16; j++) x2[j] = 0ull;

    #pragma unroll 4
    for (int k = 0; k < 32; ++k) {
        const float gk = __shfl_sync(FULLMASK, gcoef, k);
        const float q  = gk * s[k * SROW + lane];                    // conflict-free
        const u64 q2 = pk2(q, q);
        const u64* wkrow = (const u64*)&s[k * SROW];                 // broadcast LDS.64
        #pragma unroll
        for (int j = 0; j < 16; j++)
            x2[j] = fma2(q2, wkrow[j], x2[j]);
    }

    // ---- write column `lane` of X (coalesced per row) ----
    #pragma unroll
    for (int j = 0; j < 16; j++) {
        float lo, hi; upk2(x2[j], lo, hi);
        Xm[(2*j)     * 32 + lane] = lo;
        Xm[(2*j + 1) * 32 + lane] = hi;
    }
}

extern "C" void kernel_launch(void* const* d_in, const int* in_sizes, int n_in,
                              void* d_out, int out_size)
{
    const float* P = (const float*)d_in[0];
    float* X = (float*)d_out;
    const int nmat = in_sizes[0] / 1024;                             // 32x32 per matrix
    dim3 block(WPC * 32);
    dim3 grid((nmat + WPC - 1) / WPC);
    logeig_kernel<<<grid, block>>>(P, X, nmat);
}

// round 13
// speedup vs baseline: 1.2514x; 1.0783x over previous
#include <cuda_runtime.h>
#include <cuda_bf16.h>
#include <math.h>

// LogEig: X = U diag(log w) U^T for 32768 SPD 32x32 fp32 matrices.
// One matrix per warp, lane j owns column j. One-sided Jacobi (SPD: SVD == eig):
//   W <- sym(P); orthogonalize column pairs with Givens rotations (XOR tournament).
//   Converged: column k = sigma_k * u_k  ->  X = sum_k (log sigma_k / sigma_k^2) w_k w_k^T.
// Packed fma.rn.f32x2 hot loops; direct-trig rotation coefficients (2 serial MUFU);
// analytic norm updates (delta = sin2t*g - s^2*tau) refreshed exactly once per sweep;
// ballot-gated update skip.

#define FULLMASK 0xffffffffu
#define WPC 8                 // warps per CTA
#define SROW 36               // padded smem row stride (floats): 144B rows, conflict-free transpose
#define MAXSWEEP 14
#define ROTTOL 1.0e-9f        // rotate only if g^2 > ROTTOL*(|wp|^2 |wq|^2): |cos| > ~3.2e-5

typedef unsigned long long u64;

__device__ __forceinline__ u64 pk2(float lo, float hi) {
    u64 r; asm("mov.b64 %0, {%1, %2};" : "=l"(r) : "f"(lo), "f"(hi)); return r;
}
__device__ __forceinline__ void upk2(u64 v, float& lo, float& hi) {
    asm("mov.b64 {%0, %1}, %2;" : "=f"(lo), "=f"(hi) : "l"(v));
}
__device__ __forceinline__ u64 fma2(u64 a, u64 b, u64 c) {
    u64 d; asm("fma.rn.f32x2 %0, %1, %2, %3;" : "=l"(d) : "l"(a), "l"(b), "l"(c)); return d;
}
__device__ __forceinline__ u64 mul2(u64 a, u64 b) {
    u64 d; asm("mul.rn.f32x2 %0, %1, %2;" : "=l"(d) : "l"(a), "l"(b)); return d;
}
// 4-way-split packed reduction sum(a[j]*b[j]) over 16 packed regs -> scalar
__device__ __forceinline__ float redsum16(const u64* a, const u64* b) {
    u64 s0 = 0ull, s1 = 0ull, s2 = 0ull, s3 = 0ull;
    #pragma unroll
    for (int j = 0; j < 16; j += 4) {
        s0 = fma2(a[j],   b[j],   s0);
        s1 = fma2(a[j+1], b[j+1], s1);
        s2 = fma2(a[j+2], b[j+2], s2);
        s3 = fma2(a[j+3], b[j+3], s3);
    }
    float l0,h0,l1,h1,l2,h2,l3,h3;
    upk2(s0,l0,h0); upk2(s1,l1,h1); upk2(s2,l2,h2); upk2(s3,l3,h3);
    return ((l0 + h0) + (l1 + h1)) + ((l2 + h2) + (l3 + h3));
}

__global__ __launch_bounds__(WPC * 32, 3)
void logeig_kernel(const float* __restrict__ P, float* __restrict__ X, int nmat)
{
    __shared__ float sm[WPC][32 * SROW];

    const int wip  = threadIdx.x >> 5;
    const int lane = threadIdx.x & 31;
    const int mat  = blockIdx.x * WPC + wip;
    if (mat >= nmat) return;

    float* s = sm[wip];
    const float* Pm = P + (size_t)mat * 1024;
    float*       Xm = X + (size_t)mat * 1024;

    // ---- load column `lane` (coalesced) ----
    float wf[32];
    #pragma unroll
    for (int i = 0; i < 32; i++) wf[i] = Pm[i * 32 + lane];          // wf[i] = P[i][lane]

    // ---- symmetrize via padded smem transpose ----
    #pragma unroll
    for (int i = 0; i < 32; i += 4)
        *(float4*)&s[lane * SROW + i] = make_float4(wf[i], wf[i+1], wf[i+2], wf[i+3]);
    __syncwarp();
    #pragma unroll
    for (int i = 0; i < 32; i++)
        wf[i] = 0.5f * (wf[i] + s[i * SROW + lane]);                 // conflict-free
    __syncwarp();

    // ---- pack column into 16 f32x2 registers ----
    u64 w2[16];
    #pragma unroll
    for (int j = 0; j < 16; j++) w2[j] = pk2(wf[2*j], wf[2*j+1]);

    float n = 0.f;                                                    // |w|^2, refreshed each sweep

    // ---- one-sided Jacobi sweeps ----
    for (int sweep = 0; sweep < MAXSWEEP; ++sweep) {
        n = fmaxf(redsum16(w2, w2), 1e-30f);                          // exact norm refresh

        bool anyrot = false;
        for (int m = 1; m < 32; ++m) {
            // fetch partner column (u64 shuffle -> 2 SHFL each)
            u64 b2[16];
            #pragma unroll
            for (int j = 0; j < 16; j++)
                b2[j] = __shfl_xor_sync(FULLMASK, w2[j], m);
            const float nb = __shfl_xor_sync(FULLMASK, n, m);

            // dot(own, partner): bitwise-identical on both lanes of the pair
            const float g = redsum16(w2, b2);

            const bool  isp   = lane < (lane ^ m);                   // lower-index column p?
            const float alpha = isp ? n  : nb;
            const float beta  = isp ? nb : n;

            const bool rot = (g * g > ROTTOL * (alpha * beta));
            const unsigned rmask = __ballot_sync(FULLMASK, rot);     // warp-uniform
            if (!rmask) continue;                                     // nothing to rotate this substep
            anyrot = true;

            // Direct-trig Givens annihilating g (inner rotation, c >= 1/sqrt(2)):
            //   tau = beta - alpha, rho = 2g, h = sqrt(tau^2 + rho^2)
            //   cos2t = |tau|/h ; sin2t = sign(tau)*rho/h   (sign of rho PRESERVED)
            //   c = sqrt((1+cos2t)/2) ; ss = sin2t/(2c)   (sqrt & rsqrt run in parallel)
            const float tau = beta - alpha;
            const float rho = 2.f * g;
            const float ih  = rsqrtf(fmaf(tau, tau, rho * rho));     // MUFU #1
            const float cos2t = fabsf(tau) * ih;
            const float sin2t = (rho * ih) * copysignf(1.f, tau);    // keeps sign of g
            const float c2h = fmaf(0.5f, cos2t, 0.5f);               // c^2
            float c   = sqrtf(c2h);                                  // MUFU #2a
            float irc = rsqrtf(c2h);                                 // MUFU #2b (parallel with 2a)
            float ss  = 0.5f * sin2t * irc;
            if (!rot) { c = 1.f; ss = 0.f; }

            // analytic norm update (exact for the annihilating rotation):
            //   alpha' = alpha - delta ; beta' = beta + delta ; delta = sin2t*g - s^2*tau
            const float s2 = fmaf(-0.5f, cos2t, 0.5f);               // s^2
            const float delta = fmaf(-s2, tau, sin2t * g);
            const float nsel = rot ? (isp ? -delta : delta) : 0.f;
            n = fmaxf(n + nsel, 1e-30f);

            // w_p' = c*w_p - s*w_q ; w_q' = s*w_p + c*w_q
            const float vcoef = isp ? -ss : ss;
            const u64 c2 = pk2(c, c);
            const u64 v2 = pk2(vcoef, vcoef);
            #pragma unroll
            for (int j = 0; j < 16; j++)
                w2[j] = fma2(v2, b2[j], mul2(c2, w2[j]));
        }
        if (!anyrot) break;                                          // warp-uniform early exit
    }

    // ---- eigenvalue of own column: sigma^2 = n (exact: refreshed at final sweep start,
    //      which performed no rotations) ----
    const float gcoef = 0.5f * logf(n) / n;                          // log(sigma_k) / sigma_k^2

    // ---- stage converged columns to smem ----
    #pragma unroll
    for (int j = 0; j < 16; j++) {
        float lo, hi; upk2(w2[j], lo, hi);
        s[lane * SROW + 2*j]     = lo;
        s[lane * SROW + 2*j + 1] = hi;
    }
    __syncwarp();

    // ---- X = sum_k gcoef_k * w_k w_k^T : packed rank-1 accumulation ----
    u64 x2[16];
    #pragma unroll
    for (int j = 0; j < 16; j++) x2[j] = 0ull;

    #pragma unroll 4
    for (int k = 0; k < 32; ++k) {
        const float gk = __shfl_sync(FULLMASK, gcoef, k);
        const float q  = gk * s[k * SROW + lane];                    // conflict-free
        const u64 q2 = pk2(q, q);
        const u64* wkrow = (const u64*)&s[k * SROW];                 // broadcast LDS.64
        #pragma unroll
        for (int j = 0; j < 16; j++)
            x2[j] = fma2(q2, wkrow[j], x2[j]);
    }

    // ---- write column `lane` of X (coalesced per row) ----
    #pragma unroll
    for (int j = 0; j < 16; j++) {
        float lo, hi; upk2(x2[j], lo, hi);
        Xm[(2*j)     * 32 + lane] = lo;
        Xm[(2*j + 1) * 32 + lane] = hi;
    }
}

extern "C" void kernel_launch(void* const* d_in, const int* in_sizes, int n_in,
                              void* d_out, int out_size)
{
    const float* P = (const float*)d_in[0];
    float* X = (float*)d_out;
    const int nmat = in_sizes[0] / 1024;                             // 32x32 per matrix
    dim3 block(WPC * 32);
    dim3 grid((nmat + WPC - 1) / WPC);
    logeig_kernel<<<grid, block>>>(P, X, nmat);
}

// round 14
// speedup vs baseline: 1.3257x; 1.0594x over previous
#include <cuda_runtime.h>
#include <cuda_bf16.h>
#include <math.h>

// LogEig: X = U diag(log w) U^T for 32768 SPD 32x32 fp32 matrices.
// One matrix per warp, lane j owns column j. One-sided Jacobi (SPD: SVD == eig):
//   W <- sym(P); orthogonalize column pairs with Givens rotations (XOR tournament).
//   Converged: column k = sigma_k * u_k  ->  X = sum_k (log sigma_k / sigma_k^2) w_k w_k^T.
// Fast (scaled) Givens: stored column update is a single fma2/element, the cosine
// is deferred into a per-lane scale d (true col = d * stored), folded once per sweep.
// Direct-trig coefficients (2 serial MUFU); analytic true-norm updates; ballot skip.

#define FULLMASK 0xffffffffu
#define WPC 8                 // warps per CTA
#define SROW 36               // padded smem row stride (floats): 144B rows, conflict-free transpose
#define MAXSWEEP 14
#define ROTTOL 4.0e-9f        // rotate only if g^2 > ROTTOL*(|wp|^2 |wq|^2): |cos| > ~6.3e-5

typedef unsigned long long u64;

__device__ __forceinline__ u64 pk2(float lo, float hi) {
    u64 r; asm("mov.b64 %0, {%1, %2};" : "=l"(r) : "f"(lo), "f"(hi)); return r;
}
__device__ __forceinline__ void upk2(u64 v, float& lo, float& hi) {
    asm("mov.b64 {%0, %1}, %2;" : "=f"(lo), "=f"(hi) : "l"(v));
}
__device__ __forceinline__ u64 fma2(u64 a, u64 b, u64 c) {
    u64 d; asm("fma.rn.f32x2 %0, %1, %2, %3;" : "=l"(d) : "l"(a), "l"(b), "l"(c)); return d;
}
__device__ __forceinline__ u64 mul2(u64 a, u64 b) {
    u64 d; asm("mul.rn.f32x2 %0, %1, %2;" : "=l"(d) : "l"(a), "l"(b)); return d;
}
// 4-way-split packed reduction sum(a[j]*b[j]) over 16 packed regs -> scalar
__device__ __forceinline__ float redsum16(const u64* a, const u64* b) {
    u64 s0 = 0ull, s1 = 0ull, s2 = 0ull, s3 = 0ull;
    #pragma unroll
    for (int j = 0; j < 16; j += 4) {
        s0 = fma2(a[j],   b[j],   s0);
        s1 = fma2(a[j+1], b[j+1], s1);
        s2 = fma2(a[j+2], b[j+2], s2);
        s3 = fma2(a[j+3], b[j+3], s3);
    }
    float l0,h0,l1,h1,l2,h2,l3,h3;
    upk2(s0,l0,h0); upk2(s1,l1,h1); upk2(s2,l2,h2); upk2(s3,l3,h3);
    return ((l0 + h0) + (l1 + h1)) + ((l2 + h2) + (l3 + h3));
}

__global__ __launch_bounds__(WPC * 32, 3)
void logeig_kernel(const float* __restrict__ P, float* __restrict__ X, int nmat)
{
    __shared__ float sm[WPC][32 * SROW];

    const int wip  = threadIdx.x >> 5;
    const int lane = threadIdx.x & 31;
    const int mat  = blockIdx.x * WPC + wip;
    if (mat >= nmat) return;

    float* s = sm[wip];
    const float* Pm = P + (size_t)mat * 1024;
    float*       Xm = X + (size_t)mat * 1024;

    // ---- load column `lane` (coalesced) ----
    float wf[32];
    #pragma unroll
    for (int i = 0; i < 32; i++) wf[i] = Pm[i * 32 + lane];          // wf[i] = P[i][lane]

    // ---- symmetrize via padded smem transpose ----
    #pragma unroll
    for (int i = 0; i < 32; i += 4)
        *(float4*)&s[lane * SROW + i] = make_float4(wf[i], wf[i+1], wf[i+2], wf[i+3]);
    __syncwarp();
    #pragma unroll
    for (int i = 0; i < 32; i++)
        wf[i] = 0.5f * (wf[i] + s[i * SROW + lane]);                 // conflict-free
    __syncwarp();

    // ---- pack column into 16 f32x2 registers ----
    u64 w2[16];
    #pragma unroll
    for (int j = 0; j < 16; j++) w2[j] = pk2(wf[2*j], wf[2*j+1]);

    float n  = 0.f;                                                   // TRUE |col|^2, refreshed each sweep
    float d  = 1.f;                                                   // true col = d * stored col
    float id = 1.f;                                                   // ~1/d

    // ---- one-sided Jacobi sweeps (fast-Givens scaled columns) ----
    for (int sweep = 0; sweep < MAXSWEEP; ++sweep) {
        // fold accumulated scale into stored column, reset, exact norm refresh
        const u64 dd = pk2(d, d);
        #pragma unroll
        for (int j = 0; j < 16; j++) w2[j] = mul2(dd, w2[j]);
        d = 1.f; id = 1.f;
        n = fmaxf(redsum16(w2, w2), 1e-30f);

        bool anyrot = false;
        for (int m = 1; m < 32; ++m) {
            // fetch partner stored column + (norm, scale)
            u64 b2[16];
            #pragma unroll
            for (int j = 0; j < 16; j++)
                b2[j] = __shfl_xor_sync(FULLMASK, w2[j], m);
            const float nb = __shfl_xor_sync(FULLMASK, n, m);
            const float db = __shfl_xor_sync(FULLMASK, d, m);

            // true dot: g = d*db * <stored, partner-stored> (bitwise-identical on the pair)
            const float g = (d * db) * redsum16(w2, b2);

            const bool  isp   = lane < (lane ^ m);                   // lower-index column p?
            const float alpha = isp ? n  : nb;
            const float beta  = isp ? nb : n;

            const bool rot = (g * g > ROTTOL * (alpha * beta));
            const unsigned rmask = __ballot_sync(FULLMASK, rot);     // warp-uniform
            if (!rmask) continue;                                     // nothing to rotate this substep
            anyrot = true;

            // Direct-trig Givens annihilating g (inner rotation, c >= 1/sqrt(2)):
            //   tau = beta-alpha, rho = 2g, cos2t = |tau|/h, sin2t = sign(tau)*rho/h
            const float tau = beta - alpha;
            const float rho = 2.f * g;
            const float ih  = rsqrtf(fmaf(tau, tau, rho * rho));     // MUFU #1
            const float cos2t = fabsf(tau) * ih;
            float sin2t = (rho * ih) * copysignf(1.f, tau);          // keeps sign of g
            const float c2h = fmaf(0.5f, cos2t, 0.5f);               // c^2
            float c   = sqrtf(c2h);                                  // MUFU #2a
            float irc = rsqrtf(c2h);                                 // MUFU #2b (parallel)
            if (!rot) { c = 1.f; irc = 1.f; sin2t = 0.f; }           // full NaN guard: t below = 0 exactly

            const float t = (0.5f * sin2t) * (irc * irc);            // tan(theta) = s/c

            // analytic TRUE norm update: delta = sin2t*g - s^2*tau
            const float s2 = fmaf(-0.5f, cos2t, 0.5f);               // s^2 (NaN if !rot: selected away)
            const float delta = fmaf(-s2, tau, sin2t * g);
            n = fmaxf(n + (rot ? (isp ? -delta : delta) : 0.f), 1e-30f);

            // fast-Givens stored update: w_st' = w_st + u*b_st ; d' = c*d
            const float u = (isp ? -t : t) * (db * id);
            d  *= c;
            id *= irc;
            const u64 u2 = pk2(u, u);
            #pragma unroll
            for (int j = 0; j < 16; j++)
                w2[j] = fma2(u2, b2[j], w2[j]);
        }
        if (!anyrot) break;                                          // warp-uniform early exit
    }

    // ---- eigenvalue of own column: sigma^2 = n (true norm) ----
    const float gcoef = 0.5f * logf(n) / n;                          // log(sigma_k) / sigma_k^2

    // ---- stage converged TRUE columns (d * stored) to smem ----
    #pragma unroll
    for (int j = 0; j < 16; j++) {
        float lo, hi; upk2(w2[j], lo, hi);
        s[lane * SROW + 2*j]     = d * lo;
        s[lane * SROW + 2*j + 1] = d * hi;
    }
    __syncwarp();

    // ---- X = sum_k gcoef_k * w_k w_k^T : packed rank-1 accumulation ----
    u64 x2[16];
    #pragma unroll
    for (int j = 0; j < 16; j++) x2[j] = 0ull;

    #pragma unroll 4
    for (int k = 0; k < 32; ++k) {
        const float gk = __shfl_sync(FULLMASK, gcoef, k);
        const float q  = gk * s[k * SROW + lane];                    // conflict-free
        const u64 q2 = pk2(q, q);
        const u64* wkrow = (const u64*)&s[k * SROW];                 // broadcast LDS.64
        #pragma unroll
        for (int j = 0; j < 16; j++)
            x2[j] = fma2(q2, wkrow[j], x2[j]);
    }

    // ---- write column `lane` of X (coalesced per row) ----
    #pragma unroll
    for (int j = 0; j < 16; j++) {
        float lo, hi; upk2(x2[j], lo, hi);
        Xm[(2*j)     * 32 + lane] = lo;
        Xm[(2*j + 1) * 32 + lane] = hi;
    }
}

extern "C" void kernel_launch(void* const* d_in, const int* in_sizes, int n_in,
                              void* d_out, int out_size)
{
    const float* P = (const float*)d_in[0];
    float* X = (float*)d_out;
    const int nmat = in_sizes[0] / 1024;                             // 32x32 per matrix
    dim3 block(WPC * 32);
    dim3 grid((nmat + WPC - 1) / WPC);
    logeig_kernel<<<grid, block>>>(P, X, nmat);
}